// round 14
// baseline (speedup 1.0000x reference)
#include <cuda_runtime.h>
#include <cuda_fp16.h>
#include <math.h>
#include <stdint.h>

// ---------------- Problem constants ----------------
#define D_    768
#define H_    12
#define HD_   64
#define S_    197
#define L_    196
#define NB    16          // batch per image set
#define B2    32          // both image sets
#define FF_   3072
#define OUT_  512
#define QKV3  2304
#define IMG_  224
#define GRID_ 14
#define PCH_  16
#define LAYERS_ 12

// ---------------- Scratch (device globals; no allocation allowed) ----------------
__device__ float  g_x12[B2 * S_ * D_];      // residual stream (fp32)
__device__ __half g_xln[B2 * S_ * D_];      // LN output (fp16)
__device__ __half g_qkv[B2 * S_ * QKV3];    // qkv (fp16, feeds TC attention)
__device__ __half g_att[B2 * S_ * D_];      // attention out / conv_out temp (fp16)
__device__ __half g_ffh[B2 * S_ * FF_];     // MLP hidden (fp16)
__device__ __half g_im2col[B2 * L_ * D_];   // patch im2col (fp16)
__device__ float  g_cls[NB * D_];           // ln_post output (fp32)

// fp16 weight copies (B operands, [N,K] row-major)
__device__ __half g_wqkv[LAYERS_ * QKV3 * D_];
__device__ __half g_wo  [LAYERS_ * D_ * D_];
__device__ __half g_wfc [LAYERS_ * FF_ * D_];
__device__ __half g_wp  [LAYERS_ * D_ * FF_];
__device__ __half g_wcv [D_ * D_];

// ---- weight fp32 -> fp16 conversion (once per launch) ----
__global__ void cvt_half_kernel(const float4* __restrict__ in,
                                uint2* __restrict__ out, int n4)
{
    for (int i = blockIdx.x * 256 + threadIdx.x; i < n4; i += gridDim.x * 256) {
        float4 v = in[i];
        __half2 h0 = __floats2half2_rn(v.x, v.y);
        __half2 h1 = __floats2half2_rn(v.z, v.w);
        uint2 o;
        o.x = *(uint32_t*)&h0;
        o.y = *(uint32_t*)&h1;
        out[i] = o;
    }
}

// ---------------- MMA / LDSM macros ----------------
#define LDSM4(r0, r1, r2, r3, addr)                                    \
    asm volatile("ldmatrix.sync.aligned.m8n8.x4.shared.b16 "           \
                 "{%0,%1,%2,%3}, [%4];"                                \
                 : "=r"(r0), "=r"(r1), "=r"(r2), "=r"(r3) : "r"(addr))

#define LDSM4T(r0, r1, r2, r3, addr)                                   \
    asm volatile("ldmatrix.sync.aligned.m8n8.x4.trans.shared.b16 "     \
                 "{%0,%1,%2,%3}, [%4];"                                \
                 : "=r"(r0), "=r"(r1), "=r"(r2), "=r"(r3) : "r"(addr))

#define MMA_F16(d, a, b)                                               \
    asm volatile(                                                      \
        "mma.sync.aligned.m16n8k16.row.col.f32.f16.f16.f32 "           \
        "{%0,%1,%2,%3}, {%4,%5,%6,%7}, {%8,%9}, {%0,%1,%2,%3};"        \
        : "+f"((d)[0]), "+f"((d)[1]), "+f"((d)[2]), "+f"((d)[3])       \
        : "r"((a)[0]), "r"((a)[1]), "r"((a)[2]), "r"((a)[3]),          \
          "r"((b)[0]), "r"((b)[1]))

__device__ __forceinline__ uint32_t packh2(float lo, float hi) {
    __half2 h = __floats2half2_rn(lo, hi);
    return *(uint32_t*)&h;
}

// ======================================================================
// FP16 tensor-core GEMM (mma.sync), templated on M-tile:
//   C[M,N] = act( A[M,K]h @ B[N,K]h^T + bias[N] ) (+ resid[M,N])
// BMx128x64 block tile, 256 threads (8 warps 4x2), warp tile (BM/4)x64.
// BM=128: occ 2 (64KB smem). BM=64: occ 3 (48KB smem) — finer wave
// granularity for small-N GEMMs. flags: bit0 = half out, bit1 = GELU.
// ======================================================================
#define HBK   64

template <int BM>
__global__ __launch_bounds__(256, (BM == 128) ? 2 : 3) void gemm_h(
    const __half* __restrict__ A, const __half* __restrict__ B,
    const float* __restrict__ bias, const float* __restrict__ resid,
    void* __restrict__ Cv, int M, int N, int K, int flags)
{
    constexpr int ASTAGE = BM * 128;       // bytes per A stage
    constexpr int BSTAGE = 16384;          // bytes per B stage (128 rows)
    constexpr int MF     = BM / 64;        // 16-row m-frags per warp
    constexpr int WMR    = BM / 4;         // warp m-tile rows

    extern __shared__ char smb[];

    const int tid  = threadIdx.x;
    const int lane = tid & 31, wid = tid >> 5;
    const int wm = wid & 3, wn = wid >> 2;
    const int grp = lane >> 2, qid = lane & 3;
    const int bm = blockIdx.y * BM, bn = blockIdx.x * 128;

    const uint32_t smemBase = (uint32_t)__cvta_generic_to_shared(smb);

    const int lr0 = tid >> 3;
    const int lc  = tid & 7;

    float acc[MF][8][4];
    #pragma unroll
    for (int mf = 0; mf < MF; mf++)
        #pragma unroll
        for (int nf = 0; nf < 8; nf++)
            #pragma unroll
            for (int r = 0; r < 4; r++) acc[mf][nf][r] = 0.f;

    const int niter = K / HBK;

    auto issue = [&](int it, int st) {
        const int k0 = it * HBK;
        #pragma unroll
        for (int i = 0; i < BM / 32; i++) {          // A rows
            const int row = lr0 + i * 32;
            const uint32_t xoff = (uint32_t)(row * 128 + ((lc ^ (row & 7)) * 16));
            int gr = bm + row;
            int ok = (gr < M);
            const __half* src = A + (size_t)(ok ? gr : (M - 1)) * K + k0 + lc * 8;
            uint32_t dst = smemBase + st * ASTAGE + xoff;
            int sz = ok ? 16 : 0;
            asm volatile("cp.async.cg.shared.global [%0], [%1], 16, %2;"
                         :: "r"(dst), "l"(src), "r"(sz));
        }
        #pragma unroll
        for (int i = 0; i < 4; i++) {                // B rows (always 128)
            const int row = lr0 + i * 32;
            const uint32_t xoff = (uint32_t)(row * 128 + ((lc ^ (row & 7)) * 16));
            const __half* src = B + (size_t)(bn + row) * K + k0 + lc * 8;
            uint32_t dst = smemBase + 2 * ASTAGE + st * BSTAGE + xoff;
            asm volatile("cp.async.cg.shared.global [%0], [%1], 16;"
                         :: "r"(dst), "l"(src));
        }
        asm volatile("cp.async.commit_group;");
    };

    issue(0, 0);
    int stage = 0;

    const int aRowIn = lane & 15;
    const int aKHalf = lane >> 4;
    const int bMat   = lane >> 3;
    const int bRowIn = (lane & 7) + ((bMat >> 1) << 3);
    const int bKHalf = bMat & 1;

    for (int it = 0; it < niter; it++) {
        if (it + 1 < niter) {
            issue(it + 1, stage ^ 1);
            asm volatile("cp.async.wait_group 1;");
        } else {
            asm volatile("cp.async.wait_group 0;");
        }
        __syncthreads();

        const uint32_t aStage = smemBase + stage * ASTAGE;
        const uint32_t bStage = smemBase + 2 * ASTAGE + stage * BSTAGE;

        #pragma unroll
        for (int ks = 0; ks < HBK; ks += 16) {
            const int kc = ks >> 3;
            uint32_t a[MF][4], b[16];
            #pragma unroll
            for (int mf = 0; mf < MF; mf++) {
                const int row = wm * WMR + mf * 16 + aRowIn;
                const int ch  = (kc + aKHalf) ^ (row & 7);
                LDSM4(a[mf][0], a[mf][1], a[mf][2], a[mf][3],
                      aStage + (uint32_t)(row * 128 + ch * 16));
            }
            #pragma unroll
            for (int np = 0; np < 4; np++) {
                const int row = wn * 64 + np * 16 + bRowIn;
                const int ch  = (kc + bKHalf) ^ (row & 7);
                LDSM4(b[np * 4 + 0], b[np * 4 + 1], b[np * 4 + 2], b[np * 4 + 3],
                      bStage + (uint32_t)(row * 128 + ch * 16));
            }
            #pragma unroll
            for (int mf = 0; mf < MF; mf++)
                #pragma unroll
                for (int np = 0; np < 4; np++) {
                    MMA_F16(acc[mf][np * 2 + 0], a[mf], &b[np * 4 + 0]);
                    MMA_F16(acc[mf][np * 2 + 1], a[mf], &b[np * 4 + 2]);
                }
        }
        __syncthreads();
        stage ^= 1;
    }

    const int halfOut = flags & 1;
    const int act     = flags & 2;
    float* Cf = (float*)Cv;
    __half* Ch = (__half*)Cv;

    #pragma unroll
    for (int mf = 0; mf < MF; mf++) {
        #pragma unroll
        for (int hh = 0; hh < 2; hh++) {
            const int gm = bm + wm * WMR + mf * 16 + grp + hh * 8;
            if (gm >= M) continue;
            #pragma unroll
            for (int nf = 0; nf < 8; nf++) {
                const int gn = bn + wn * 64 + nf * 8 + 2 * qid;
                float v0 = acc[mf][nf][hh * 2 + 0];
                float v1 = acc[mf][nf][hh * 2 + 1];
                if (bias) { v0 += bias[gn]; v1 += bias[gn + 1]; }
                if (act) {
                    v0 = v0 / (1.f + __expf(-1.702f * v0));
                    v1 = v1 / (1.f + __expf(-1.702f * v1));
                }
                if (resid) {
                    const float* rp = resid + (size_t)gm * N + gn;
                    v0 += rp[0]; v1 += rp[1];
                }
                if (halfOut) {
                    __half2 h = __floats2half2_rn(v0, v1);
                    *(__half2*)(Ch + (size_t)gm * N + gn) = h;
                } else {
                    float2 o; o.x = v0; o.y = v1;
                    *(float2*)(Cf + (size_t)gm * N + gn) = o;
                }
            }
        }
    }
}

// ======================================================================
// Tensor-core attention (mma.sync). One block per (head, batch), 8 warps.
// 13 K-tiles (208 cols; 197-207 masked). For batches b >= bias_base the
// cls-row bias comes straight from pred (!=0 ? 0 : -1e30).
// ======================================================================
#define SATT   224
#define ATT_MAT 28672
#define ATT_SMEM (3 * ATT_MAT)
#define NKT    13                   // K tiles of 16 (208 columns)

__global__ __launch_bounds__(256) void attn_tc(
    const __half* __restrict__ qkv, const float* __restrict__ pred,
    int bias_base, __half* __restrict__ out)
{
    extern __shared__ char smb[];
    const int h = blockIdx.x, b = blockIdx.y;
    const int tid = threadIdx.x;
    const int lane = tid & 31, wid = tid >> 5;
    const uint32_t base = (uint32_t)__cvta_generic_to_shared(smb);

    for (int i = tid; i < S_ * 24; i += 256) {
        int s = i / 24, rem = i % 24;
        int m3 = rem >> 3, c = rem & 7;
        const uint4 v = *(const uint4*)(qkv + ((size_t)(b * S_ + s)) * QKV3
                                        + m3 * D_ + h * HD_ + c * 8);
        uint4 w = v;
        if (m3 == 0) {
            const __half2 sc = __floats2half2_rn(0.125f, 0.125f);
            __half2* hp = (__half2*)&w;
            hp[0] = __hmul2(hp[0], sc); hp[1] = __hmul2(hp[1], sc);
            hp[2] = __hmul2(hp[2], sc); hp[3] = __hmul2(hp[3], sc);
        }
        *(uint4*)(smb + m3 * ATT_MAT + s * 128 + ((c ^ (s & 7)) * 16)) = w;
    }
    // zero-pad rows 197..207 only (tiles beyond 13 never read)
    for (int i = tid; i < (NKT * 16 - S_) * 24; i += 256) {
        int r = S_ + i / 24, rem = i % 24;
        int m3 = rem >> 3, c = rem & 7;
        *(uint4*)(smb + m3 * ATT_MAT + r * 128 + ((c ^ (r & 7)) * 16)) =
            make_uint4(0, 0, 0, 0);
    }
    __syncthreads();

    const int grp = lane >> 2, qid = lane & 3;
    const int aRow = lane & 15, aK = lane >> 4;
    const int bRow = (lane & 7) + ((lane >> 4) << 3);
    const int bK   = (lane >> 3) & 1;
    const int vRow = (lane & 7) + (((lane >> 3) & 1) << 3);
    const int vC   = lane >> 4;

    const bool hasBias = (pred != nullptr) && (b >= bias_base);
    const float* predRow = hasBias ? (pred + (size_t)(b - bias_base) * L_)
                                   : nullptr;

    for (int chunk = wid; chunk < 13; chunk += 8) {
        const int mbase = chunk * 16;

        float sc[2 * NKT][4];
        #pragma unroll
        for (int j = 0; j < 2 * NKT; j++)
            #pragma unroll
            for (int e = 0; e < 4; e++) sc[j][e] = 0.f;

        #pragma unroll
        for (int t = 0; t < 4; t++) {
            uint32_t a[4];
            const int ar = mbase + aRow;
            LDSM4(a[0], a[1], a[2], a[3],
                  base + (uint32_t)(ar * 128 + (((2 * t + aK) ^ (ar & 7)) * 16)));
            #pragma unroll
            for (int np = 0; np < NKT; np++) {
                uint32_t bb[4];
                const int br = np * 16 + bRow;
                LDSM4(bb[0], bb[1], bb[2], bb[3],
                      base + (uint32_t)(ATT_MAT + br * 128
                                        + (((2 * t + bK) ^ (br & 7)) * 16)));
                MMA_F16(sc[np * 2 + 0], a, &bb[0]);
                MMA_F16(sc[np * 2 + 1], a, &bb[2]);
            }
        }

        const bool dobias = hasBias && (mbase == 0) && (grp == 0);
        float m0 = -1e30f, m1 = -1e30f;
        #pragma unroll
        for (int j = 0; j < 2 * NKT; j++) {
            const int col = j * 8 + 2 * qid;
            if (dobias) {
                if (col >= 1 && col < S_)
                    sc[j][0] += (predRow[col - 1] != 0.f) ? 0.f : -1e30f;
                if (col + 1 < S_)
                    sc[j][1] += (predRow[col] != 0.f) ? 0.f : -1e30f;
            }
            if (col >= S_)     { sc[j][0] = -1e30f; sc[j][2] = -1e30f; }
            if (col + 1 >= S_) { sc[j][1] = -1e30f; sc[j][3] = -1e30f; }
            m0 = fmaxf(m0, fmaxf(sc[j][0], sc[j][1]));
            m1 = fmaxf(m1, fmaxf(sc[j][2], sc[j][3]));
        }
        m0 = fmaxf(m0, __shfl_xor_sync(0xffffffffu, m0, 1));
        m0 = fmaxf(m0, __shfl_xor_sync(0xffffffffu, m0, 2));
        m1 = fmaxf(m1, __shfl_xor_sync(0xffffffffu, m1, 1));
        m1 = fmaxf(m1, __shfl_xor_sync(0xffffffffu, m1, 2));

        float s0 = 0.f, s1 = 0.f;
        #pragma unroll
        for (int j = 0; j < 2 * NKT; j++) {
            sc[j][0] = __expf(sc[j][0] - m0);
            sc[j][1] = __expf(sc[j][1] - m0);
            sc[j][2] = __expf(sc[j][2] - m1);
            sc[j][3] = __expf(sc[j][3] - m1);
            s0 += sc[j][0] + sc[j][1];
            s1 += sc[j][2] + sc[j][3];
        }
        s0 += __shfl_xor_sync(0xffffffffu, s0, 1);
        s0 += __shfl_xor_sync(0xffffffffu, s0, 2);
        s1 += __shfl_xor_sync(0xffffffffu, s1, 1);
        s1 += __shfl_xor_sync(0xffffffffu, s1, 2);

        float ov[8][4];
        #pragma unroll
        for (int j = 0; j < 8; j++)
            #pragma unroll
            for (int e = 0; e < 4; e++) ov[j][e] = 0.f;

        #pragma unroll
        for (int t = 0; t < NKT; t++) {
            uint32_t a[4];
            a[0] = packh2(sc[2 * t][0],     sc[2 * t][1]);
            a[1] = packh2(sc[2 * t][2],     sc[2 * t][3]);
            a[2] = packh2(sc[2 * t + 1][0], sc[2 * t + 1][1]);
            a[3] = packh2(sc[2 * t + 1][2], sc[2 * t + 1][3]);
            const int vr = t * 16 + vRow;
            #pragma unroll
            for (int np = 0; np < 4; np++) {
                uint32_t vv[4];
                const int vc = 2 * np + vC;
                LDSM4T(vv[0], vv[1], vv[2], vv[3],
                       base + (uint32_t)(2 * ATT_MAT + vr * 128
                                         + ((vc ^ (vr & 7)) * 16)));
                MMA_F16(ov[np * 2 + 0], a, &vv[0]);
                MMA_F16(ov[np * 2 + 1], a, &vv[2]);
            }
        }

        const float inv0 = 1.f / s0, inv1 = 1.f / s1;
        const int q0 = mbase + grp, q1 = q0 + 8;
        #pragma unroll
        for (int j = 0; j < 8; j++) {
            const int col = h * HD_ + j * 8 + 2 * qid;
            if (q0 < S_) {
                __half2 o = __floats2half2_rn(ov[j][0] * inv0, ov[j][1] * inv0);
                *(__half2*)(out + (size_t)(b * S_ + q0) * D_ + col) = o;
            }
            if (q1 < S_) {
                __half2 o = __floats2half2_rn(ov[j][2] * inv1, ov[j][3] * inv1);
                *(__half2*)(out + (size_t)(b * S_ + q1) * D_ + col) = o;
            }
        }
    }
}

// ======================================================================
// LayerNorm: warp-per-row (8 rows / 256-thr block), float4 IO, pure
// shuffle reductions — no smem, no __syncthreads.
// ======================================================================
__device__ __forceinline__ void ln_store(float* yr, int idx, float4 o) {
    ((float4*)yr)[idx] = o;
}
__device__ __forceinline__ void ln_store(__half* yr, int idx, float4 o) {
    __half2 h0 = __floats2half2_rn(o.x, o.y);
    __half2 h1 = __floats2half2_rn(o.z, o.w);
    uint2 u; u.x = *(uint32_t*)&h0; u.y = *(uint32_t*)&h1;
    ((uint2*)yr)[idx] = u;
}

template <typename TO>
__global__ __launch_bounds__(256) void ln_kernel(
    const float* __restrict__ x, long in_stride,
    TO* __restrict__ y, long out_stride,
    const float* __restrict__ g, const float* __restrict__ b, int rows)
{
    const int wid = threadIdx.x >> 5, lane = threadIdx.x & 31;
    const int r = blockIdx.x * 8 + wid;
    if (r >= rows) return;

    const float4* xr = (const float4*)(x + (size_t)r * in_stride);
    TO* yr = y + (size_t)r * out_stride;

    float4 v[6];
    float s = 0.f;
    #pragma unroll
    for (int i = 0; i < 6; i++) {
        v[i] = xr[lane + 32 * i];
        s += (v[i].x + v[i].y) + (v[i].z + v[i].w);
    }
    #pragma unroll
    for (int o = 16; o > 0; o >>= 1) s += __shfl_xor_sync(0xffffffffu, s, o);
    const float mu = s * (1.f / 768.f);

    float ss = 0.f;
    #pragma unroll
    for (int i = 0; i < 6; i++) {
        v[i].x -= mu; v[i].y -= mu; v[i].z -= mu; v[i].w -= mu;
        ss += v[i].x * v[i].x + v[i].y * v[i].y
            + v[i].z * v[i].z + v[i].w * v[i].w;
    }
    #pragma unroll
    for (int o = 16; o > 0; o >>= 1) ss += __shfl_xor_sync(0xffffffffu, ss, o);
    const float rs = rsqrtf(ss * (1.f / 768.f) + 1e-5f);

    const float4* g4 = (const float4*)g;
    const float4* b4 = (const float4*)b;
    #pragma unroll
    for (int i = 0; i < 6; i++) {
        const float4 gg = g4[lane + 32 * i];
        const float4 bb = b4[lane + 32 * i];
        float4 o;
        o.x = v[i].x * rs * gg.x + bb.x;
        o.y = v[i].y * rs * gg.y + bb.y;
        o.z = v[i].z * rs * gg.z + bb.z;
        o.w = v[i].w * rs * gg.w + bb.w;
        ln_store(yr, lane + 32 * i, o);
    }
}

// ======================================================================
// Fused mask_combine + LayerNorm for the masking layers.
// ======================================================================
__global__ __launch_bounds__(256) void ln_mask_kernel(
    float* __restrict__ x, const float* __restrict__ pred,
    __half* __restrict__ y,
    const float* __restrict__ g, const float* __restrict__ b)
{
    const int wid = threadIdx.x >> 5, lane = threadIdx.x & 31;
    const int r = blockIdx.x * 8 + wid;
    if (r >= B2 * S_) return;

    float4* xr = (float4*)(x + (size_t)r * D_);
    __half* yr = y + (size_t)r * D_;

    const bool comb = (r < NB * S_);
    float4 v[6];

    if (comb) {
        const int bidx = r / S_, s_ = r % S_;
        const float mf = (s_ == 0) ? 1.f : pred[bidx * L_ + (s_ - 1)];
        const float4* x2r = (const float4*)(x + ((size_t)NB * S_ + r) * D_);
        #pragma unroll
        for (int i = 0; i < 6; i++) {
            float4 a = xr[lane + 32 * i];
            float4 c = x2r[lane + 32 * i];
            v[i].x = 2.f * c.x * mf + a.x;
            v[i].y = 2.f * c.y * mf + a.y;
            v[i].z = 2.f * c.z * mf + a.z;
            v[i].w = 2.f * c.w * mf + a.w;
            xr[lane + 32 * i] = v[i];
        }
    } else {
        #pragma unroll
        for (int i = 0; i < 6; i++) v[i] = xr[lane + 32 * i];
    }

    float s = 0.f;
    #pragma unroll
    for (int i = 0; i < 6; i++)
        s += (v[i].x + v[i].y) + (v[i].z + v[i].w);
    #pragma unroll
    for (int o = 16; o > 0; o >>= 1) s += __shfl_xor_sync(0xffffffffu, s, o);
    const float mu = s * (1.f / 768.f);

    float ss = 0.f;
    #pragma unroll
    for (int i = 0; i < 6; i++) {
        v[i].x -= mu; v[i].y -= mu; v[i].z -= mu; v[i].w -= mu;
        ss += v[i].x * v[i].x + v[i].y * v[i].y
            + v[i].z * v[i].z + v[i].w * v[i].w;
    }
    #pragma unroll
    for (int o = 16; o > 0; o >>= 1) ss += __shfl_xor_sync(0xffffffffu, ss, o);
    const float rs = rsqrtf(ss * (1.f / 768.f) + 1e-5f);

    const float4* g4 = (const float4*)g;
    const float4* b4 = (const float4*)b;
    #pragma unroll
    for (int i = 0; i < 6; i++) {
        const float4 gg = g4[lane + 32 * i];
        const float4 bb = b4[lane + 32 * i];
        float4 o;
        o.x = v[i].x * rs * gg.x + bb.x;
        o.y = v[i].y * rs * gg.y + bb.y;
        o.z = v[i].z * rs * gg.z + bb.z;
        o.w = v[i].w * rs * gg.w + bb.w;
        ln_store(yr, lane + 32 * i, o);
    }
}

// ======================================================================
// Patch embed helpers
// ======================================================================
__global__ void im2col_kernel(const float* __restrict__ masked,
                              const float* __restrict__ prompted,
                              __half* __restrict__ col)
{
    int idx = blockIdx.x * 256 + threadIdx.x;
    const int total = B2 * L_ * D_;
    if (idx >= total) return;
    int k = idx % D_;
    int m = idx / D_;
    int b = m / L_, l = m % L_;
    int gy = l / GRID_, gx = l % GRID_;
    int c = k >> 8, rem = k & 255;
    int py = rem >> 4, px = rem & 15;
    const float* src = (b < NB) ? (masked + (size_t)b * 3 * IMG_ * IMG_)
                                : (prompted + (size_t)(b - NB) * 3 * IMG_ * IMG_);
    col[idx] = __float2half_rn(
        src[((size_t)c * IMG_ + gy * PCH_ + py) * IMG_ + gx * PCH_ + px]);
}

__global__ void embed_kernel(const __half* __restrict__ conv_out,
                             const float* __restrict__ cls_emb,
                             const float* __restrict__ pos,
                             float* __restrict__ x)
{
    int idx = blockIdx.x * 256 + threadIdx.x;
    const int total = B2 * S_ * D_;
    if (idx >= total) return;
    int d = idx % D_;
    int bs = idx / D_;
    int s = bs % S_, b = bs / S_;
    float v = (s == 0) ? cls_emb[d]
                       : __half2float(conv_out[((size_t)b * L_ + (s - 1)) * D_ + d]);
    x[idx] = v + pos[s * D_ + d];
}

__global__ void proj_out_kernel(const float* __restrict__ cls,
                                const float* __restrict__ proj,
                                float* __restrict__ out)
{
    int n = blockIdx.x * 256 + threadIdx.x;
    int m = blockIdx.y;
    if (n >= OUT_) return;
    float s = 0.f;
    #pragma unroll 4
    for (int k = 0; k < D_; k++) s += cls[m * D_ + k] * proj[(size_t)k * OUT_ + n];
    out[m * OUT_ + n] = s;
}

// ======================================================================
// Host orchestration
// ======================================================================
template <typename T>
static T* symaddr_t(const void* s) {
    void* p = nullptr;
    cudaGetSymbolAddress(&p, s);
    return (T*)p;
}

template <int BM>
static void run_gemm(const __half* A, const __half* B, const float* bias,
                     const float* resid, void* C, int M, int N, int K, int flags,
                     cudaStream_t st)
{
    const int smem = 2 * (BM * 128) + 2 * 16384;
    dim3 grid(N / 128, (M + BM - 1) / BM);
    gemm_h<BM><<<grid, 256, smem, st>>>(A, B, bias, resid, C, M, N, K, flags);
}

static void run_cvt(const float* in, __half* out, long n, cudaStream_t st)
{
    int n4 = (int)(n / 4);
    int blocks = (n4 + 255) / 256;
    if (blocks > 16384) blocks = 16384;
    cvt_half_kernel<<<blocks, 256, 0, st>>>((const float4*)in, (uint2*)out, n4);
}

struct Ctx {
    float *x12, *cls;
    __half *xln, *qkv, *att, *ffh, *col;
    const __half *Wqkv, *Wo, *Wfc, *Wp;
    const float *bqkv, *bo, *ln1g, *ln1b, *ln2g, *ln2b, *bfc, *bp;
    const float *pred;
};

static void run_block(const Ctx& c, float* x, int Bn, int layer,
                      const float* bias_pred, int bias_base, int maskfuse,
                      cudaStream_t st)
{
    const int M = Bn * S_;
    const int lgrid = (M + 7) / 8;
    if (maskfuse) {
        ln_mask_kernel<<<lgrid, 256, 0, st>>>(x, c.pred, c.xln,
                                              c.ln1g + layer * D_,
                                              c.ln1b + layer * D_);
    } else {
        ln_kernel<__half><<<lgrid, 256, 0, st>>>(x, D_, c.xln, D_,
                                      c.ln1g + layer * D_, c.ln1b + layer * D_, M);
    }
    run_gemm<64>(c.xln, c.Wqkv + (size_t)layer * QKV3 * D_, c.bqkv + layer * QKV3,
             nullptr, c.qkv, M, QKV3, D_, 1, st);
    attn_tc<<<dim3(H_, Bn), 256, ATT_SMEM, st>>>(c.qkv, bias_pred, bias_base, c.att);
    run_gemm<64>(c.att, c.Wo + (size_t)layer * D_ * D_, c.bo + layer * D_,
             x, x, M, D_, D_, 0, st);
    ln_kernel<__half><<<lgrid, 256, 0, st>>>(x, D_, c.xln, D_,
                                  c.ln2g + layer * D_, c.ln2b + layer * D_, M);
    run_gemm<64>(c.xln, c.Wfc + (size_t)layer * FF_ * D_, c.bfc + layer * FF_,
             nullptr, c.ffh, M, FF_, D_, 1 | 2, st);
    run_gemm<64>(c.ffh, c.Wp + (size_t)layer * D_ * FF_, c.bp + layer * D_,
             x, x, M, D_, FF_, 0, st);
}

extern "C" void kernel_launch(void* const* d_in, const int* in_sizes, int n_in,
                              void* d_out, int out_size)
{
    const float* masked   = (const float*)d_in[0];
    const float* prompted = (const float*)d_in[1];
    const float* pred     = (const float*)d_in[2];
    const float* conv_w   = (const float*)d_in[3];
    const float* cls_emb  = (const float*)d_in[4];
    const float* pos_emb  = (const float*)d_in[5];
    const float* lnpre_g  = (const float*)d_in[6];
    const float* lnpre_b  = (const float*)d_in[7];

    const float* Wqkv_raw = (const float*)d_in[8];
    const float* bqkv     = (const float*)d_in[9];
    const float* Wo_raw   = (const float*)d_in[10];
    const float* bo       = (const float*)d_in[11];
    const float* ln1g     = (const float*)d_in[12];
    const float* ln1b     = (const float*)d_in[13];
    const float* ln2g     = (const float*)d_in[14];
    const float* ln2b     = (const float*)d_in[15];
    const float* Wfc_raw  = (const float*)d_in[16];
    const float* bfc      = (const float*)d_in[17];
    const float* Wp_raw   = (const float*)d_in[18];
    const float* bp       = (const float*)d_in[19];
    const float* lnpost_g = (const float*)d_in[20];
    const float* lnpost_b = (const float*)d_in[21];
    const float* proj     = (const float*)d_in[22];
    float* out = (float*)d_out;

    static cudaStream_t s2 = nullptr;
    static cudaEvent_t ev[4];
    if (!s2) {
        cudaStreamCreateWithFlags(&s2, cudaStreamNonBlocking);
        for (int i = 0; i < 4; i++)
            cudaEventCreateWithFlags(&ev[i], cudaEventDisableTiming);
    }
    cudaStream_t s0 = 0;

    Ctx c;
    c.x12  = symaddr_t<float>(g_x12);
    c.xln  = symaddr_t<__half>(g_xln);
    c.qkv  = symaddr_t<__half>(g_qkv);
    c.att  = symaddr_t<__half>(g_att);
    c.ffh  = symaddr_t<__half>(g_ffh);
    c.col  = symaddr_t<__half>(g_im2col);
    c.cls  = symaddr_t<float>(g_cls);
    c.pred = pred;

    __half* wqkv = symaddr_t<__half>(g_wqkv);
    __half* wo   = symaddr_t<__half>(g_wo);
    __half* wfc  = symaddr_t<__half>(g_wfc);
    __half* wp   = symaddr_t<__half>(g_wp);
    __half* wcv  = symaddr_t<__half>(g_wcv);

    c.Wqkv = wqkv; c.bqkv = bqkv;
    c.Wo   = wo;   c.bo   = bo;
    c.ln1g = ln1g; c.ln1b = ln1b;
    c.ln2g = ln2g; c.ln2b = ln2b;
    c.Wfc  = wfc;  c.bfc  = bfc;
    c.Wp   = wp;   c.bp   = bp;

    cudaFuncSetAttribute(attn_tc, cudaFuncAttributeMaxDynamicSharedMemorySize,
                         ATT_SMEM);
    cudaFuncSetAttribute(gemm_h<128>, cudaFuncAttributeMaxDynamicSharedMemorySize,
                         2 * (128 * 128) + 2 * 16384);
    cudaFuncSetAttribute(gemm_h<64>, cudaFuncAttributeMaxDynamicSharedMemorySize,
                         2 * (64 * 128) + 2 * 16384);

    // ---- fork: weight conversion on s2 (layer 0 first), embed path on s0 ----
    cudaEventRecord(ev[0], s0);
    cudaStreamWaitEvent(s2, ev[0], 0);

    run_cvt(conv_w, wcv, (long)D_ * D_, s2);
    cudaEventRecord(ev[1], s2);                  // conv weights ready
    run_cvt(Wqkv_raw, wqkv, (long)QKV3 * D_, s2);
    run_cvt(Wo_raw,   wo,   (long)D_ * D_, s2);
    run_cvt(Wfc_raw,  wfc,  (long)FF_ * D_, s2);
    run_cvt(Wp_raw,   wp,   (long)D_ * FF_, s2);
    cudaEventRecord(ev[3], s2);                  // layer-0 weights ready
    run_cvt(Wqkv_raw + (long)QKV3 * D_, wqkv + (long)QKV3 * D_,
            (long)(LAYERS_ - 1) * QKV3 * D_, s2);
    run_cvt(Wo_raw + (long)D_ * D_, wo + (long)D_ * D_,
            (long)(LAYERS_ - 1) * D_ * D_, s2);
    run_cvt(Wfc_raw + (long)FF_ * D_, wfc + (long)FF_ * D_,
            (long)(LAYERS_ - 1) * FF_ * D_, s2);
    run_cvt(Wp_raw + (long)D_ * FF_, wp + (long)D_ * FF_,
            (long)(LAYERS_ - 1) * D_ * FF_, s2);
    cudaEventRecord(ev[2], s2);                  // all weights ready

    {
        const int total = B2 * L_ * D_;
        im2col_kernel<<<(total + 255) / 256, 256, 0, s0>>>(masked, prompted, c.col);
        cudaStreamWaitEvent(s0, ev[1], 0);       // need wcv
        run_gemm<128>(c.col, wcv, nullptr, nullptr, c.att, B2 * L_, D_, D_, 1, s0);
        const int tot2 = B2 * S_ * D_;
        embed_kernel<<<(tot2 + 255) / 256, 256, 0, s0>>>(c.att, cls_emb, pos_emb, c.x12);
        ln_kernel<float><<<(B2 * S_ + 7) / 8, 256, 0, s0>>>(
            c.x12, D_, c.x12, D_, lnpre_g, lnpre_b, B2 * S_);
    }

    cudaStreamWaitEvent(s0, ev[3], 0);           // layer-0 weights
    run_block(c, c.x12, B2, 0, nullptr, 0, 0, s0);
    cudaStreamWaitEvent(s0, ev[2], 0);           // all weights
    for (int i = 1; i < 10; i++)
        run_block(c, c.x12, B2, i, nullptr, 0, 0, s0);

    // ---- masking phase: merged block per layer; fused combine+LN1 ----
    float* x = c.x12;
    const int layers2[2] = {10, 11};
    for (int t = 0; t < 2; t++)
        run_block(c, c.x12, B2, layers2[t], pred, NB, 1, s0);

    ln_kernel<float><<<(NB + 7) / 8, 256, 0, s0>>>(x, (long)S_ * D_, c.cls, D_,
                                                   lnpost_g, lnpost_b, NB);
    proj_out_kernel<<<dim3((OUT_ + 255) / 256, NB), 256, 0, s0>>>(c.cls, proj, out);

    (void)in_sizes; (void)n_in; (void)out_size;
}

// round 15
// speedup vs baseline: 1.1322x; 1.1322x over previous
#include <cuda_runtime.h>
#include <cuda_fp16.h>
#include <math.h>
#include <stdint.h>

// ---------------- Problem constants ----------------
#define D_    768
#define H_    12
#define HD_   64
#define S_    197
#define L_    196
#define NB    16          // batch per image set
#define B2    32          // both image sets
#define FF_   3072
#define OUT_  512
#define QKV3  2304
#define IMG_  224
#define GRID_ 14
#define PCH_  16
#define LAYERS_ 12

// ---------------- Scratch (device globals; no allocation allowed) ----------------
__device__ float  g_x12[B2 * S_ * D_];      // residual stream (fp32)
__device__ __half g_xln[B2 * S_ * D_];      // LN output (fp16)
__device__ __half g_qkv[B2 * S_ * QKV3];    // qkv (fp16, feeds TC attention)
__device__ __half g_att[B2 * S_ * D_];      // attention out / conv_out temp (fp16)
__device__ __half g_ffh[B2 * S_ * FF_];     // MLP hidden (fp16)
__device__ __half g_im2col[B2 * L_ * D_];   // patch im2col (fp16)
__device__ float  g_cls[NB * D_];           // ln_post output (fp32)

// fp16 weight copies (B operands, [N,K] row-major)
__device__ __half g_wqkv[LAYERS_ * QKV3 * D_];
__device__ __half g_wo  [LAYERS_ * D_ * D_];
__device__ __half g_wfc [LAYERS_ * FF_ * D_];
__device__ __half g_wp  [LAYERS_ * D_ * FF_];
__device__ __half g_wcv [D_ * D_];

// ---- weight fp32 -> fp16 conversion (once per launch) ----
__global__ void cvt_half_kernel(const float4* __restrict__ in,
                                uint2* __restrict__ out, int n4)
{
    for (int i = blockIdx.x * 256 + threadIdx.x; i < n4; i += gridDim.x * 256) {
        float4 v = in[i];
        __half2 h0 = __floats2half2_rn(v.x, v.y);
        __half2 h1 = __floats2half2_rn(v.z, v.w);
        uint2 o;
        o.x = *(uint32_t*)&h0;
        o.y = *(uint32_t*)&h1;
        out[i] = o;
    }
}

// ---------------- MMA / LDSM macros ----------------
#define LDSM4(r0, r1, r2, r3, addr)                                    \
    asm volatile("ldmatrix.sync.aligned.m8n8.x4.shared.b16 "           \
                 "{%0,%1,%2,%3}, [%4];"                                \
                 : "=r"(r0), "=r"(r1), "=r"(r2), "=r"(r3) : "r"(addr))

#define LDSM4T(r0, r1, r2, r3, addr)                                   \
    asm volatile("ldmatrix.sync.aligned.m8n8.x4.trans.shared.b16 "     \
                 "{%0,%1,%2,%3}, [%4];"                                \
                 : "=r"(r0), "=r"(r1), "=r"(r2), "=r"(r3) : "r"(addr))

#define MMA_F16(d, a, b)                                               \
    asm volatile(                                                      \
        "mma.sync.aligned.m16n8k16.row.col.f32.f16.f16.f32 "           \
        "{%0,%1,%2,%3}, {%4,%5,%6,%7}, {%8,%9}, {%0,%1,%2,%3};"        \
        : "+f"((d)[0]), "+f"((d)[1]), "+f"((d)[2]), "+f"((d)[3])       \
        : "r"((a)[0]), "r"((a)[1]), "r"((a)[2]), "r"((a)[3]),          \
          "r"((b)[0]), "r"((b)[1]))

__device__ __forceinline__ uint32_t packh2(float lo, float hi) {
    __half2 h = __floats2half2_rn(lo, hi);
    return *(uint32_t*)&h;
}

// ======================================================================
// FP16 tensor-core GEMM (mma.sync):
//   C[M,N] = act( A[M,K]h @ B[N,K]h^T + bias[N] ) (+ resid[M,N])
// 128x128x64 block tile, 256 threads (8 warps 4x2), warp tile 32x64.
// flags: bit0 = half output, bit1 = GELU.
// ======================================================================
#define HBK   64
#define HST   16384

__global__ __launch_bounds__(256, 2) void gemm_h(
    const __half* __restrict__ A, const __half* __restrict__ B,
    const float* __restrict__ bias, const float* __restrict__ resid,
    void* __restrict__ Cv, int M, int N, int K, int flags)
{
    extern __shared__ char smb[];

    const int tid  = threadIdx.x;
    const int lane = tid & 31, wid = tid >> 5;
    const int wm = wid & 3, wn = wid >> 2;
    const int grp = lane >> 2, qid = lane & 3;
    const int bm = blockIdx.y * 128, bn = blockIdx.x * 128;

    const uint32_t smemBase = (uint32_t)__cvta_generic_to_shared(smb);

    const int lr0 = tid >> 3;
    const int lc  = tid & 7;

    float acc[2][8][4];
    #pragma unroll
    for (int mf = 0; mf < 2; mf++)
        #pragma unroll
        for (int nf = 0; nf < 8; nf++)
            #pragma unroll
            for (int r = 0; r < 4; r++) acc[mf][nf][r] = 0.f;

    const int niter = K / HBK;

    auto issue = [&](int it, int st) {
        const int k0 = it * HBK;
        #pragma unroll
        for (int i = 0; i < 4; i++) {
            const int row = lr0 + i * 32;
            const uint32_t xoff = (uint32_t)(row * 128 + ((lc ^ (row & 7)) * 16));
            {
                int gr = bm + row;
                int ok = (gr < M);
                const __half* src = A + (size_t)(ok ? gr : (M - 1)) * K + k0 + lc * 8;
                uint32_t dst = smemBase + st * HST + xoff;
                int sz = ok ? 16 : 0;
                asm volatile("cp.async.cg.shared.global [%0], [%1], 16, %2;"
                             :: "r"(dst), "l"(src), "r"(sz));
            }
            {
                const __half* src = B + (size_t)(bn + row) * K + k0 + lc * 8;
                uint32_t dst = smemBase + 2 * HST + st * HST + xoff;
                asm volatile("cp.async.cg.shared.global [%0], [%1], 16;"
                             :: "r"(dst), "l"(src));
            }
        }
        asm volatile("cp.async.commit_group;");
    };

    issue(0, 0);
    int stage = 0;

    const int aRowIn = lane & 15;
    const int aKHalf = lane >> 4;
    const int bMat   = lane >> 3;
    const int bRowIn = (lane & 7) + ((bMat >> 1) << 3);
    const int bKHalf = bMat & 1;

    for (int it = 0; it < niter; it++) {
        if (it + 1 < niter) {
            issue(it + 1, stage ^ 1);
            asm volatile("cp.async.wait_group 1;");
        } else {
            asm volatile("cp.async.wait_group 0;");
        }
        __syncthreads();

        const uint32_t aStage = smemBase + stage * HST;
        const uint32_t bStage = smemBase + 2 * HST + stage * HST;

        #pragma unroll
        for (int ks = 0; ks < HBK; ks += 16) {
            const int kc = ks >> 3;
            uint32_t a[2][4], b[16];
            #pragma unroll
            for (int mf = 0; mf < 2; mf++) {
                const int row = wm * 32 + mf * 16 + aRowIn;
                const int ch  = (kc + aKHalf) ^ (row & 7);
                LDSM4(a[mf][0], a[mf][1], a[mf][2], a[mf][3],
                      aStage + (uint32_t)(row * 128 + ch * 16));
            }
            #pragma unroll
            for (int np = 0; np < 4; np++) {
                const int row = wn * 64 + np * 16 + bRowIn;
                const int ch  = (kc + bKHalf) ^ (row & 7);
                LDSM4(b[np * 4 + 0], b[np * 4 + 1], b[np * 4 + 2], b[np * 4 + 3],
                      bStage + (uint32_t)(row * 128 + ch * 16));
            }
            #pragma unroll
            for (int mf = 0; mf < 2; mf++)
                #pragma unroll
                for (int np = 0; np < 4; np++) {
                    MMA_F16(acc[mf][np * 2 + 0], a[mf], &b[np * 4 + 0]);
                    MMA_F16(acc[mf][np * 2 + 1], a[mf], &b[np * 4 + 2]);
                }
        }
        __syncthreads();
        stage ^= 1;
    }

    const int halfOut = flags & 1;
    const int act     = flags & 2;
    float* Cf = (float*)Cv;
    __half* Ch = (__half*)Cv;

    #pragma unroll
    for (int mf = 0; mf < 2; mf++) {
        #pragma unroll
        for (int hh = 0; hh < 2; hh++) {
            const int gm = bm + wm * 32 + mf * 16 + grp + hh * 8;
            if (gm >= M) continue;
            #pragma unroll
            for (int nf = 0; nf < 8; nf++) {
                const int gn = bn + wn * 64 + nf * 8 + 2 * qid;
                float v0 = acc[mf][nf][hh * 2 + 0];
                float v1 = acc[mf][nf][hh * 2 + 1];
                if (bias) { v0 += bias[gn]; v1 += bias[gn + 1]; }
                if (act) {
                    v0 = v0 / (1.f + __expf(-1.702f * v0));
                    v1 = v1 / (1.f + __expf(-1.702f * v1));
                }
                if (resid) {
                    const float* rp = resid + (size_t)gm * N + gn;
                    v0 += rp[0]; v1 += rp[1];
                }
                if (halfOut) {
                    __half2 h = __floats2half2_rn(v0, v1);
                    *(__half2*)(Ch + (size_t)gm * N + gn) = h;
                } else {
                    float2 o; o.x = v0; o.y = v1;
                    *(float2*)(Cf + (size_t)gm * N + gn) = o;
                }
            }
        }
    }
}

// ======================================================================
// Tensor-core attention (mma.sync). One block per (head, batch), 8 warps.
// 13 K-tiles (208 cols; 197-207 masked). For batches b >= bias_base the
// cls-row bias comes straight from pred (!=0 ? 0 : -1e30).
// ======================================================================
#define SATT   224
#define ATT_MAT 28672
#define ATT_SMEM (3 * ATT_MAT)
#define NKT    13                   // K tiles of 16 (208 columns)

__global__ __launch_bounds__(256) void attn_tc(
    const __half* __restrict__ qkv, const float* __restrict__ pred,
    int bias_base, __half* __restrict__ out)
{
    extern __shared__ char smb[];
    const int h = blockIdx.x, b = blockIdx.y;
    const int tid = threadIdx.x;
    const int lane = tid & 31, wid = tid >> 5;
    const uint32_t base = (uint32_t)__cvta_generic_to_shared(smb);

    for (int i = tid; i < S_ * 24; i += 256) {
        int s = i / 24, rem = i % 24;
        int m3 = rem >> 3, c = rem & 7;
        const uint4 v = *(const uint4*)(qkv + ((size_t)(b * S_ + s)) * QKV3
                                        + m3 * D_ + h * HD_ + c * 8);
        uint4 w = v;
        if (m3 == 0) {
            const __half2 sc = __floats2half2_rn(0.125f, 0.125f);
            __half2* hp = (__half2*)&w;
            hp[0] = __hmul2(hp[0], sc); hp[1] = __hmul2(hp[1], sc);
            hp[2] = __hmul2(hp[2], sc); hp[3] = __hmul2(hp[3], sc);
        }
        *(uint4*)(smb + m3 * ATT_MAT + s * 128 + ((c ^ (s & 7)) * 16)) = w;
    }
    // zero-pad rows 197..207 (tiles beyond 13 never read)
    for (int i = tid; i < (NKT * 16 - S_) * 24; i += 256) {
        int r = S_ + i / 24, rem = i % 24;
        int m3 = rem >> 3, c = rem & 7;
        *(uint4*)(smb + m3 * ATT_MAT + r * 128 + ((c ^ (r & 7)) * 16)) =
            make_uint4(0, 0, 0, 0);
    }
    __syncthreads();

    const int grp = lane >> 2, qid = lane & 3;
    const int aRow = lane & 15, aK = lane >> 4;
    const int bRow = (lane & 7) + ((lane >> 4) << 3);
    const int bK   = (lane >> 3) & 1;
    const int vRow = (lane & 7) + (((lane >> 3) & 1) << 3);
    const int vC   = lane >> 4;

    const bool hasBias = (pred != nullptr) && (b >= bias_base);
    const float* predRow = hasBias ? (pred + (size_t)(b - bias_base) * L_)
                                   : nullptr;

    for (int chunk = wid; chunk < 13; chunk += 8) {
        const int mbase = chunk * 16;

        float sc[2 * NKT][4];
        #pragma unroll
        for (int j = 0; j < 2 * NKT; j++)
            #pragma unroll
            for (int e = 0; e < 4; e++) sc[j][e] = 0.f;

        #pragma unroll
        for (int t = 0; t < 4; t++) {
            uint32_t a[4];
            const int ar = mbase + aRow;
            LDSM4(a[0], a[1], a[2], a[3],
                  base + (uint32_t)(ar * 128 + (((2 * t + aK) ^ (ar & 7)) * 16)));
            #pragma unroll
            for (int np = 0; np < NKT; np++) {
                uint32_t bb[4];
                const int br = np * 16 + bRow;
                LDSM4(bb[0], bb[1], bb[2], bb[3],
                      base + (uint32_t)(ATT_MAT + br * 128
                                        + (((2 * t + bK) ^ (br & 7)) * 16)));
                MMA_F16(sc[np * 2 + 0], a, &bb[0]);
                MMA_F16(sc[np * 2 + 1], a, &bb[2]);
            }
        }

        const bool dobias = hasBias && (mbase == 0) && (grp == 0);
        float m0 = -1e30f, m1 = -1e30f;
        #pragma unroll
        for (int j = 0; j < 2 * NKT; j++) {
            const int col = j * 8 + 2 * qid;
            if (dobias) {
                if (col >= 1 && col < S_)
                    sc[j][0] += (predRow[col - 1] != 0.f) ? 0.f : -1e30f;
                if (col + 1 < S_)
                    sc[j][1] += (predRow[col] != 0.f) ? 0.f : -1e30f;
            }
            if (col >= S_)     { sc[j][0] = -1e30f; sc[j][2] = -1e30f; }
            if (col + 1 >= S_) { sc[j][1] = -1e30f; sc[j][3] = -1e30f; }
            m0 = fmaxf(m0, fmaxf(sc[j][0], sc[j][1]));
            m1 = fmaxf(m1, fmaxf(sc[j][2], sc[j][3]));
        }
        m0 = fmaxf(m0, __shfl_xor_sync(0xffffffffu, m0, 1));
        m0 = fmaxf(m0, __shfl_xor_sync(0xffffffffu, m0, 2));
        m1 = fmaxf(m1, __shfl_xor_sync(0xffffffffu, m1, 1));
        m1 = fmaxf(m1, __shfl_xor_sync(0xffffffffu, m1, 2));

        float s0 = 0.f, s1 = 0.f;
        #pragma unroll
        for (int j = 0; j < 2 * NKT; j++) {
            sc[j][0] = __expf(sc[j][0] - m0);
            sc[j][1] = __expf(sc[j][1] - m0);
            sc[j][2] = __expf(sc[j][2] - m1);
            sc[j][3] = __expf(sc[j][3] - m1);
            s0 += sc[j][0] + sc[j][1];
            s1 += sc[j][2] + sc[j][3];
        }
        s0 += __shfl_xor_sync(0xffffffffu, s0, 1);
        s0 += __shfl_xor_sync(0xffffffffu, s0, 2);
        s1 += __shfl_xor_sync(0xffffffffu, s1, 1);
        s1 += __shfl_xor_sync(0xffffffffu, s1, 2);

        float ov[8][4];
        #pragma unroll
        for (int j = 0; j < 8; j++)
            #pragma unroll
            for (int e = 0; e < 4; e++) ov[j][e] = 0.f;

        #pragma unroll
        for (int t = 0; t < NKT; t++) {
            uint32_t a[4];
            a[0] = packh2(sc[2 * t][0],     sc[2 * t][1]);
            a[1] = packh2(sc[2 * t][2],     sc[2 * t][3]);
            a[2] = packh2(sc[2 * t + 1][0], sc[2 * t + 1][1]);
            a[3] = packh2(sc[2 * t + 1][2], sc[2 * t + 1][3]);
            const int vr = t * 16 + vRow;
            #pragma unroll
            for (int np = 0; np < 4; np++) {
                uint32_t vv[4];
                const int vc = 2 * np + vC;
                LDSM4T(vv[0], vv[1], vv[2], vv[3],
                       base + (uint32_t)(2 * ATT_MAT + vr * 128
                                         + ((vc ^ (vr & 7)) * 16)));
                MMA_F16(ov[np * 2 + 0], a, &vv[0]);
                MMA_F16(ov[np * 2 + 1], a, &vv[2]);
            }
        }

        const float inv0 = 1.f / s0, inv1 = 1.f / s1;
        const int q0 = mbase + grp, q1 = q0 + 8;
        #pragma unroll
        for (int j = 0; j < 8; j++) {
            const int col = h * HD_ + j * 8 + 2 * qid;
            if (q0 < S_) {
                __half2 o = __floats2half2_rn(ov[j][0] * inv0, ov[j][1] * inv0);
                *(__half2*)(out + (size_t)(b * S_ + q0) * D_ + col) = o;
            }
            if (q1 < S_) {
                __half2 o = __floats2half2_rn(ov[j][2] * inv1, ov[j][3] * inv1);
                *(__half2*)(out + (size_t)(b * S_ + q1) * D_ + col) = o;
            }
        }
    }
}

// ======================================================================
// LayerNorm: warp-per-row (8 rows / 256-thr block), float4 IO, pure
// shuffle reductions — no smem, no __syncthreads.
// ======================================================================
__device__ __forceinline__ void ln_store(float* yr, int idx, float4 o) {
    ((float4*)yr)[idx] = o;
}
__device__ __forceinline__ void ln_store(__half* yr, int idx, float4 o) {
    __half2 h0 = __floats2half2_rn(o.x, o.y);
    __half2 h1 = __floats2half2_rn(o.z, o.w);
    uint2 u; u.x = *(uint32_t*)&h0; u.y = *(uint32_t*)&h1;
    ((uint2*)yr)[idx] = u;
}

template <typename TO>
__global__ __launch_bounds__(256) void ln_kernel(
    const float* __restrict__ x, long in_stride,
    TO* __restrict__ y, long out_stride,
    const float* __restrict__ g, const float* __restrict__ b, int rows)
{
    const int wid = threadIdx.x >> 5, lane = threadIdx.x & 31;
    const int r = blockIdx.x * 8 + wid;
    if (r >= rows) return;

    const float4* xr = (const float4*)(x + (size_t)r * in_stride);
    TO* yr = y + (size_t)r * out_stride;

    float4 v[6];
    float s = 0.f;
    #pragma unroll
    for (int i = 0; i < 6; i++) {
        v[i] = xr[lane + 32 * i];
        s += (v[i].x + v[i].y) + (v[i].z + v[i].w);
    }
    #pragma unroll
    for (int o = 16; o > 0; o >>= 1) s += __shfl_xor_sync(0xffffffffu, s, o);
    const float mu = s * (1.f / 768.f);

    float ss = 0.f;
    #pragma unroll
    for (int i = 0; i < 6; i++) {
        v[i].x -= mu; v[i].y -= mu; v[i].z -= mu; v[i].w -= mu;
        ss += v[i].x * v[i].x + v[i].y * v[i].y
            + v[i].z * v[i].z + v[i].w * v[i].w;
    }
    #pragma unroll
    for (int o = 16; o > 0; o >>= 1) ss += __shfl_xor_sync(0xffffffffu, ss, o);
    const float rs = rsqrtf(ss * (1.f / 768.f) + 1e-5f);

    const float4* g4 = (const float4*)g;
    const float4* b4 = (const float4*)b;
    #pragma unroll
    for (int i = 0; i < 6; i++) {
        const float4 gg = g4[lane + 32 * i];
        const float4 bb = b4[lane + 32 * i];
        float4 o;
        o.x = v[i].x * rs * gg.x + bb.x;
        o.y = v[i].y * rs * gg.y + bb.y;
        o.z = v[i].z * rs * gg.z + bb.z;
        o.w = v[i].w * rs * gg.w + bb.w;
        ln_store(yr, lane + 32 * i, o);
    }
}

// ======================================================================
// Fused mask_combine + LayerNorm for the masking layers.
// ======================================================================
__global__ __launch_bounds__(256) void ln_mask_kernel(
    float* __restrict__ x, const float* __restrict__ pred,
    __half* __restrict__ y,
    const float* __restrict__ g, const float* __restrict__ b)
{
    const int wid = threadIdx.x >> 5, lane = threadIdx.x & 31;
    const int r = blockIdx.x * 8 + wid;
    if (r >= B2 * S_) return;

    float4* xr = (float4*)(x + (size_t)r * D_);
    __half* yr = y + (size_t)r * D_;

    const bool comb = (r < NB * S_);
    float4 v[6];

    if (comb) {
        const int bidx = r / S_, s_ = r % S_;
        const float mf = (s_ == 0) ? 1.f : pred[bidx * L_ + (s_ - 1)];
        const float4* x2r = (const float4*)(x + ((size_t)NB * S_ + r) * D_);
        #pragma unroll
        for (int i = 0; i < 6; i++) {
            float4 a = xr[lane + 32 * i];
            float4 c = x2r[lane + 32 * i];
            v[i].x = 2.f * c.x * mf + a.x;
            v[i].y = 2.f * c.y * mf + a.y;
            v[i].z = 2.f * c.z * mf + a.z;
            v[i].w = 2.f * c.w * mf + a.w;
            xr[lane + 32 * i] = v[i];
        }
    } else {
        #pragma unroll
        for (int i = 0; i < 6; i++) v[i] = xr[lane + 32 * i];
    }

    float s = 0.f;
    #pragma unroll
    for (int i = 0; i < 6; i++)
        s += (v[i].x + v[i].y) + (v[i].z + v[i].w);
    #pragma unroll
    for (int o = 16; o > 0; o >>= 1) s += __shfl_xor_sync(0xffffffffu, s, o);
    const float mu = s * (1.f / 768.f);

    float ss = 0.f;
    #pragma unroll
    for (int i = 0; i < 6; i++) {
        v[i].x -= mu; v[i].y -= mu; v[i].z -= mu; v[i].w -= mu;
        ss += v[i].x * v[i].x + v[i].y * v[i].y
            + v[i].z * v[i].z + v[i].w * v[i].w;
    }
    #pragma unroll
    for (int o = 16; o > 0; o >>= 1) ss += __shfl_xor_sync(0xffffffffu, ss, o);
    const float rs = rsqrtf(ss * (1.f / 768.f) + 1e-5f);

    const float4* g4 = (const float4*)g;
    const float4* b4 = (const float4*)b;
    #pragma unroll
    for (int i = 0; i < 6; i++) {
        const float4 gg = g4[lane + 32 * i];
        const float4 bb = b4[lane + 32 * i];
        float4 o;
        o.x = v[i].x * rs * gg.x + bb.x;
        o.y = v[i].y * rs * gg.y + bb.y;
        o.z = v[i].z * rs * gg.z + bb.z;
        o.w = v[i].w * rs * gg.w + bb.w;
        ln_store(yr, lane + 32 * i, o);
    }
}

// ======================================================================
// Patch embed helpers
// ======================================================================
__global__ void im2col_kernel(const float* __restrict__ masked,
                              const float* __restrict__ prompted,
                              __half* __restrict__ col)
{
    int idx = blockIdx.x * 256 + threadIdx.x;
    const int total = B2 * L_ * D_;
    if (idx >= total) return;
    int k = idx % D_;
    int m = idx / D_;
    int b = m / L_, l = m % L_;
    int gy = l / GRID_, gx = l % GRID_;
    int c = k >> 8, rem = k & 255;
    int py = rem >> 4, px = rem & 15;
    const float* src = (b < NB) ? (masked + (size_t)b * 3 * IMG_ * IMG_)
                                : (prompted + (size_t)(b - NB) * 3 * IMG_ * IMG_);
    col[idx] = __float2half_rn(
        src[((size_t)c * IMG_ + gy * PCH_ + py) * IMG_ + gx * PCH_ + px]);
}

__global__ void embed_kernel(const __half* __restrict__ conv_out,
                             const float* __restrict__ cls_emb,
                             const float* __restrict__ pos,
                             float* __restrict__ x)
{
    int idx = blockIdx.x * 256 + threadIdx.x;
    const int total = B2 * S_ * D_;
    if (idx >= total) return;
    int d = idx % D_;
    int bs = idx / D_;
    int s = bs % S_, b = bs / S_;
    float v = (s == 0) ? cls_emb[d]
                       : __half2float(conv_out[((size_t)b * L_ + (s - 1)) * D_ + d]);
    x[idx] = v + pos[s * D_ + d];
}

__global__ void proj_out_kernel(const float* __restrict__ cls,
                                const float* __restrict__ proj,
                                float* __restrict__ out)
{
    int n = blockIdx.x * 256 + threadIdx.x;
    int m = blockIdx.y;
    if (n >= OUT_) return;
    float s = 0.f;
    #pragma unroll 4
    for (int k = 0; k < D_; k++) s += cls[m * D_ + k] * proj[(size_t)k * OUT_ + n];
    out[m * OUT_ + n] = s;
}

// ======================================================================
// Host orchestration
// ======================================================================
template <typename T>
static T* symaddr_t(const void* s) {
    void* p = nullptr;
    cudaGetSymbolAddress(&p, s);
    return (T*)p;
}

#define GEMM_SMEM (4 * HST)   // 65,536 B

static void run_gemm(const __half* A, const __half* B, const float* bias,
                     const float* resid, void* C, int M, int N, int K, int flags,
                     cudaStream_t st)
{
    dim3 grid(N / 128, (M + 127) / 128);
    gemm_h<<<grid, 256, GEMM_SMEM, st>>>(A, B, bias, resid, C, M, N, K, flags);
}

static void run_cvt(const float* in, __half* out, long n, cudaStream_t st)
{
    int n4 = (int)(n / 4);
    int blocks = (n4 + 255) / 256;
    if (blocks > 16384) blocks = 16384;
    cvt_half_kernel<<<blocks, 256, 0, st>>>((const float4*)in, (uint2*)out, n4);
}

struct Ctx {
    float *x12, *cls;
    __half *xln, *qkv, *att, *ffh, *col;
    const __half *Wqkv, *Wo, *Wfc, *Wp;
    const float *bqkv, *bo, *ln1g, *ln1b, *ln2g, *ln2b, *bfc, *bp;
    const float *pred;
};

static void run_block(const Ctx& c, float* x, int Bn, int layer,
                      const float* bias_pred, int bias_base, int maskfuse,
                      cudaStream_t st)
{
    const int M = Bn * S_;
    const int lgrid = (M + 7) / 8;
    if (maskfuse) {
        ln_mask_kernel<<<lgrid, 256, 0, st>>>(x, c.pred, c.xln,
                                              c.ln1g + layer * D_,
                                              c.ln1b + layer * D_);
    } else {
        ln_kernel<__half><<<lgrid, 256, 0, st>>>(x, D_, c.xln, D_,
                                      c.ln1g + layer * D_, c.ln1b + layer * D_, M);
    }
    run_gemm(c.xln, c.Wqkv + (size_t)layer * QKV3 * D_, c.bqkv + layer * QKV3,
             nullptr, c.qkv, M, QKV3, D_, 1, st);
    attn_tc<<<dim3(H_, Bn), 256, ATT_SMEM, st>>>(c.qkv, bias_pred, bias_base, c.att);
    run_gemm(c.att, c.Wo + (size_t)layer * D_ * D_, c.bo + layer * D_,
             x, x, M, D_, D_, 0, st);
    ln_kernel<__half><<<lgrid, 256, 0, st>>>(x, D_, c.xln, D_,
                                  c.ln2g + layer * D_, c.ln2b + layer * D_, M);
    run_gemm(c.xln, c.Wfc + (size_t)layer * FF_ * D_, c.bfc + layer * FF_,
             nullptr, c.ffh, M, FF_, D_, 1 | 2, st);
    run_gemm(c.ffh, c.Wp + (size_t)layer * D_ * FF_, c.bp + layer * D_,
             x, x, M, D_, FF_, 0, st);
}

extern "C" void kernel_launch(void* const* d_in, const int* in_sizes, int n_in,
                              void* d_out, int out_size)
{
    const float* masked   = (const float*)d_in[0];
    const float* prompted = (const float*)d_in[1];
    const float* pred     = (const float*)d_in[2];
    const float* conv_w   = (const float*)d_in[3];
    const float* cls_emb  = (const float*)d_in[4];
    const float* pos_emb  = (const float*)d_in[5];
    const float* lnpre_g  = (const float*)d_in[6];
    const float* lnpre_b  = (const float*)d_in[7];

    const float* Wqkv_raw = (const float*)d_in[8];
    const float* bqkv     = (const float*)d_in[9];
    const float* Wo_raw   = (const float*)d_in[10];
    const float* bo       = (const float*)d_in[11];
    const float* ln1g     = (const float*)d_in[12];
    const float* ln1b     = (const float*)d_in[13];
    const float* ln2g     = (const float*)d_in[14];
    const float* ln2b     = (const float*)d_in[15];
    const float* Wfc_raw  = (const float*)d_in[16];
    const float* bfc      = (const float*)d_in[17];
    const float* Wp_raw   = (const float*)d_in[18];
    const float* bp       = (const float*)d_in[19];
    const float* lnpost_g = (const float*)d_in[20];
    const float* lnpost_b = (const float*)d_in[21];
    const float* proj     = (const float*)d_in[22];
    float* out = (float*)d_out;

    static cudaStream_t s2 = nullptr;
    static cudaEvent_t ev[4];
    if (!s2) {
        cudaStreamCreateWithFlags(&s2, cudaStreamNonBlocking);
        for (int i = 0; i < 4; i++)
            cudaEventCreateWithFlags(&ev[i], cudaEventDisableTiming);
    }
    cudaStream_t s0 = 0;

    Ctx c;
    c.x12  = symaddr_t<float>(g_x12);
    c.xln  = symaddr_t<__half>(g_xln);
    c.qkv  = symaddr_t<__half>(g_qkv);
    c.att  = symaddr_t<__half>(g_att);
    c.ffh  = symaddr_t<__half>(g_ffh);
    c.col  = symaddr_t<__half>(g_im2col);
    c.cls  = symaddr_t<float>(g_cls);
    c.pred = pred;

    __half* wqkv = symaddr_t<__half>(g_wqkv);
    __half* wo   = symaddr_t<__half>(g_wo);
    __half* wfc  = symaddr_t<__half>(g_wfc);
    __half* wp   = symaddr_t<__half>(g_wp);
    __half* wcv  = symaddr_t<__half>(g_wcv);

    c.Wqkv = wqkv; c.bqkv = bqkv;
    c.Wo   = wo;   c.bo   = bo;
    c.ln1g = ln1g; c.ln1b = ln1b;
    c.ln2g = ln2g; c.ln2b = ln2b;
    c.Wfc  = wfc;  c.bfc  = bfc;
    c.Wp   = wp;   c.bp   = bp;

    cudaFuncSetAttribute(attn_tc, cudaFuncAttributeMaxDynamicSharedMemorySize,
                         ATT_SMEM);
    cudaFuncSetAttribute(gemm_h, cudaFuncAttributeMaxDynamicSharedMemorySize,
                         GEMM_SMEM);

    // ---- fork: weight conversion on s2 (layer 0 first), embed path on s0 ----
    cudaEventRecord(ev[0], s0);
    cudaStreamWaitEvent(s2, ev[0], 0);

    run_cvt(conv_w, wcv, (long)D_ * D_, s2);
    cudaEventRecord(ev[1], s2);                  // conv weights ready
    run_cvt(Wqkv_raw, wqkv, (long)QKV3 * D_, s2);
    run_cvt(Wo_raw,   wo,   (long)D_ * D_, s2);
    run_cvt(Wfc_raw,  wfc,  (long)FF_ * D_, s2);
    run_cvt(Wp_raw,   wp,   (long)D_ * FF_, s2);
    cudaEventRecord(ev[3], s2);                  // layer-0 weights ready
    run_cvt(Wqkv_raw + (long)QKV3 * D_, wqkv + (long)QKV3 * D_,
            (long)(LAYERS_ - 1) * QKV3 * D_, s2);
    run_cvt(Wo_raw + (long)D_ * D_, wo + (long)D_ * D_,
            (long)(LAYERS_ - 1) * D_ * D_, s2);
    run_cvt(Wfc_raw + (long)FF_ * D_, wfc + (long)FF_ * D_,
            (long)(LAYERS_ - 1) * FF_ * D_, s2);
    run_cvt(Wp_raw + (long)D_ * FF_, wp + (long)D_ * FF_,
            (long)(LAYERS_ - 1) * D_ * FF_, s2);
    cudaEventRecord(ev[2], s2);                  // all weights ready

    {
        const int total = B2 * L_ * D_;
        im2col_kernel<<<(total + 255) / 256, 256, 0, s0>>>(masked, prompted, c.col);
        cudaStreamWaitEvent(s0, ev[1], 0);       // need wcv
        run_gemm(c.col, wcv, nullptr, nullptr, c.att, B2 * L_, D_, D_, 1, s0);
        const int tot2 = B2 * S_ * D_;
        embed_kernel<<<(tot2 + 255) / 256, 256, 0, s0>>>(c.att, cls_emb, pos_emb, c.x12);
        ln_kernel<float><<<(B2 * S_ + 7) / 8, 256, 0, s0>>>(
            c.x12, D_, c.x12, D_, lnpre_g, lnpre_b, B2 * S_);
    }

    cudaStreamWaitEvent(s0, ev[3], 0);           // layer-0 weights
    run_block(c, c.x12, B2, 0, nullptr, 0, 0, s0);
    cudaStreamWaitEvent(s0, ev[2], 0);           // all weights
    for (int i = 1; i < 10; i++)
        run_block(c, c.x12, B2, i, nullptr, 0, 0, s0);

    // ---- masking phase: merged block per layer; fused combine+LN1 ----
    float* x = c.x12;
    const int layers2[2] = {10, 11};
    for (int t = 0; t < 2; t++)
        run_block(c, c.x12, B2, layers2[t], pred, NB, 1, s0);

    ln_kernel<float><<<(NB + 7) / 8, 256, 0, s0>>>(x, (long)S_ * D_, c.cls, D_,
                                                   lnpost_g, lnpost_b, NB);
    proj_out_kernel<<<dim3((OUT_ + 255) / 256, NB), 256, 0, s0>>>(c.cls, proj, out);

    (void)in_sizes; (void)n_in; (void)out_size;
}